// round 14
// baseline (speedup 1.0000x reference)
#include <cuda_runtime.h>
#include <cuda_fp16.h>
#include <math.h>
#include <stdint.h>

// Problem constants
#define NB   4
#define LL   2048
#define CC   1024
#define KK   7
#define MM   (NB * LL)   // 8192

// Scratch (allocation-free rule: __device__ globals)
__device__ __half g_xh[MM * CC];     // fp16 x (emitted by conv_ln_gelu)
__device__ __half g_wih[CC * CC];    // fp16 Wi
__device__ __half g_woh[CC * CC];    // fp16 Wout
__device__ __half g_woh7[KK * CC];   // fp16 Wo (offset head)
__device__ __half g_wmh7[KK * CC];   // fp16 Wm (mask head)
__device__ __half g_xph[MM * CC];    // x_proj (fp16)
__device__ __half g_xdw[MM * CC];    // conv+LN+GELU result (fp16)
__device__ __half g_samph[MM * CC];  // sampled (fp16)
__device__ float  g_recw[MM * 16];   // per-position blend weights (wf[8], wc[8])
__device__ int    g_reci[MM * 16];   // per-position gather indices (pf[8], pc[8])

// ---------------------------------------------------------------------------
// helpers
// ---------------------------------------------------------------------------
__device__ __forceinline__ uint32_t smem_u32(const void* p) {
    uint32_t a;
    asm("{ .reg .u64 t; cvta.to.shared.u64 t, %1; cvt.u32.u64 %0, t; }"
        : "=r"(a) : "l"(p));
    return a;
}

__device__ __forceinline__ void mma_f16(float* d, const uint32_t* a,
                                        const uint32_t* b) {
    asm volatile(
        "mma.sync.aligned.m16n8k16.row.col.f32.f16.f16.f32 "
        "{%0,%1,%2,%3}, {%4,%5,%6,%7}, {%8,%9}, {%0,%1,%2,%3};"
        : "+f"(d[0]), "+f"(d[1]), "+f"(d[2]), "+f"(d[3])
        : "r"(a[0]), "r"(a[1]), "r"(a[2]), "r"(a[3]),
          "r"(b[0]), "r"(b[1]));
}

#define LDSM4(r0, r1, r2, r3, addr)                                           \
    asm volatile("ldmatrix.sync.aligned.m8n8.x4.shared.b16 {%0,%1,%2,%3}, [%4];" \
                 : "=r"(r0), "=r"(r1), "=r"(r2), "=r"(r3) : "r"(addr))

#define CP_ASYNC16(dst, src) \
    asm volatile("cp.async.cg.shared.global [%0], [%1], 16;" :: "r"(dst), "l"(src))
#define CP_COMMIT() asm volatile("cp.async.commit_group;" ::: "memory")
#define CP_WAIT1()  asm volatile("cp.async.wait_group 1;" ::: "memory")

__device__ __forceinline__ void store_out(float2 v, float* p) {
    *(float2*)p = v;
}
__device__ __forceinline__ void store_out(float2 v, __half* p) {
    *(__half2*)p = __floats2half2_rn(v.x, v.y);
}

// ---------------------------------------------------------------------------
// fp32 -> fp16 conversion (weights)
// ---------------------------------------------------------------------------
__global__ __launch_bounds__(256)
void cvt_f16(const float4* __restrict__ in, uint2* __restrict__ out, int n4) {
    int i = blockIdx.x * blockDim.x + threadIdx.x;
    if (i < n4) {
        float4 v = in[i];
        __half2 h0 = __floats2half2_rn(v.x, v.y);
        __half2 h1 = __floats2half2_rn(v.z, v.w);
        uint2 o;
        o.x = *(uint32_t*)&h0;
        o.y = *(uint32_t*)&h1;
        out[i] = o;
    }
}

// ---------------------------------------------------------------------------
// fp16 mma.sync GEMM (NT): C[m,n] = sum_k A[m,k]*B[n,k] + bias[n]
// 128x128 CTA tile, BK=64, 8 warps (4x2), 32x64 warp tile, 256 threads,
// 3-stage cp.async, XOR swizzle, ldmatrix. Output templated.
// (Proven best configuration: ~54us/GEMM = fp32-accum HMMA ceiling.)
// ---------------------------------------------------------------------------
#define TILE_BYTES 16384
#define SMEM_F16   (3 * 2 * TILE_BYTES)

__device__ __forceinline__ void stage_ab(uint32_t base,
                                         const __half* __restrict__ A,
                                         const __half* __restrict__ B,
                                         int bm, int bn, int k0, int tid) {
#pragma unroll
    for (int i = 0; i < 4; ++i) {
        int f = i * 256 + tid;
        int row = f >> 3, c4 = f & 7;
        uint32_t dst = base + row * 128 + ((c4 ^ (row & 7)) << 4);
        const __half* src = A + (size_t)(bm + row) * 1024 + k0 + c4 * 8;
        CP_ASYNC16(dst, src);
    }
#pragma unroll
    for (int i = 0; i < 4; ++i) {
        int f = i * 256 + tid;
        int row = f >> 3, c4 = f & 7;
        uint32_t dst = base + TILE_BYTES + row * 128 + ((c4 ^ (row & 7)) << 4);
        const __half* src = B + (size_t)(bn + row) * 1024 + k0 + c4 * 8;
        CP_ASYNC16(dst, src);
    }
}

template <typename OT>
__global__ __launch_bounds__(256, 2)
void mma_gemm(const __half* __restrict__ A, const __half* __restrict__ B,
              const float* __restrict__ bias, OT* __restrict__ Cout) {
    extern __shared__ char dyn_smem[];
    const uint32_t sb = smem_u32(dyn_smem);

    const int tid  = threadIdx.x;
    const int wid  = tid >> 5;
    const int lane = tid & 31;
    const int g    = lane >> 2;
    const int tig  = lane & 3;
    const int wm   = wid >> 1;     // 0..3  (32 rows each)
    const int wn   = wid & 1;      // 0..1  (64 cols each)
    const int bm = blockIdx.y * 128;
    const int bn = blockIdx.x * 128;

    float d[2][8][4];
#pragma unroll
    for (int i = 0; i < 2; ++i)
#pragma unroll
        for (int j = 0; j < 8; ++j)
#pragma unroll
            for (int r = 0; r < 4; ++r) d[i][j][r] = 0.f;

    const int aHi = (lane >> 4) & 1;
    uint32_t aRowOff[2], aSw[2];
#pragma unroll
    for (int i = 0; i < 2; ++i) {
        int rowA = wm * 32 + i * 16 + (lane & 15);
        aRowOff[i] = (uint32_t)(rowA * 128);
        aSw[i] = (uint32_t)(rowA & 7);
    }
    const int bHi = (lane >> 3) & 1;
    uint32_t bRowOff[4], bSw[4];
#pragma unroll
    for (int j2 = 0; j2 < 4; ++j2) {
        int rowB = wn * 64 + j2 * 16 + ((lane & 16) >> 1) + (lane & 7);
        bRowOff[j2] = (uint32_t)(rowB * 128);
        bSw[j2] = (uint32_t)(rowB & 7);
    }

    stage_ab(sb + 0 * 32768, A, B, bm, bn, 0, tid);
    CP_COMMIT();
    stage_ab(sb + 1 * 32768, A, B, bm, bn, 64, tid);
    CP_COMMIT();

#pragma unroll 1
    for (int s = 0; s < 16; ++s) {
        CP_WAIT1();
        __syncthreads();

        if (s + 2 < 16)
            stage_ab(sb + ((s + 2) % 3) * 32768, A, B, bm, bn,
                     (s + 2) * 64, tid);
        CP_COMMIT();

        const uint32_t aBase = sb + (s % 3) * 32768;
        const uint32_t bBase = aBase + TILE_BYTES;

#pragma unroll
        for (int ks = 0; ks < 4; ++ks) {
            const uint32_t granA = (uint32_t)(2 * ks + aHi);
            const uint32_t granB = (uint32_t)(2 * ks + bHi);
            uint32_t af[2][4];
#pragma unroll
            for (int i = 0; i < 2; ++i) {
                uint32_t addr = aBase + aRowOff[i] + ((granA ^ aSw[i]) << 4);
                LDSM4(af[i][0], af[i][1], af[i][2], af[i][3], addr);
            }
            uint32_t bf[8][2];
#pragma unroll
            for (int j2 = 0; j2 < 4; ++j2) {
                uint32_t addr = bBase + bRowOff[j2] + ((granB ^ bSw[j2]) << 4);
                LDSM4(bf[2 * j2][0], bf[2 * j2][1],
                      bf[2 * j2 + 1][0], bf[2 * j2 + 1][1], addr);
            }
#pragma unroll
            for (int i = 0; i < 2; ++i)
#pragma unroll
                for (int j = 0; j < 8; ++j)
                    mma_f16(d[i][j], af[i], bf[j]);
        }
    }

#pragma unroll
    for (int i = 0; i < 2; ++i) {
        int row = bm + wm * 32 + i * 16 + g;
        OT* o0 = Cout + (size_t)row * 1024 + bn + wn * 64;
        OT* o1 = o0 + 8 * 1024;
#pragma unroll
        for (int j = 0; j < 8; ++j) {
            int col = j * 8 + tig * 2;
            float2 bb = *(const float2*)&bias[bn + wn * 64 + col];
            float2 v0, v1;
            v0.x = d[i][j][0] + bb.x;
            v0.y = d[i][j][1] + bb.y;
            v1.x = d[i][j][2] + bb.x;
            v1.y = d[i][j][3] + bb.y;
            store_out(v0, o0 + col);
            store_out(v1, o1 + col);
        }
    }
}

// ---------------------------------------------------------------------------
// Kernel A: depthwise conv(k=3,pad=1) + LayerNorm + exact GELU -> x_dw fp16,
// plus fp16 copy of its own x row (feeds GEMM1).
// TWO positions per 512-thread block (half-block per position, fully
// parallel reductions). Adjacent positions share conv rows + weights via L1.
// ---------------------------------------------------------------------------
__global__ __launch_bounds__(512)
void conv_ln_gelu(const float* __restrict__ x,
                  const float* __restrict__ dw_w, const float* __restrict__ dw_b,
                  const float* __restrict__ ln_g, const float* __restrict__ ln_b,
                  __half* __restrict__ xdw, __half* __restrict__ xh) {
    const int half = threadIdx.x >> 8;            // 0 or 1
    const int tid  = threadIdx.x & 255;           // 0..255 within half
    const int nl   = blockIdx.x * 2 + half;
    const int l    = nl & (LL - 1);
    const int lane = threadIdx.x & 31;
    const int wlocal = (threadIdx.x >> 5) & 7;    // warp within half
    const int c0 = tid * 4;

    const float* x0 = x + (size_t)nl * CC;

    float4 xm = *(const float4*)(x0 + c0);
    float4 xl = (l > 0)      ? *(const float4*)(x0 + c0 - CC) : make_float4(0,0,0,0);
    float4 xr = (l < LL - 1) ? *(const float4*)(x0 + c0 + CC) : make_float4(0,0,0,0);

    // emit fp16 copy of this row (feeds GEMM1)
    {
        __half2 hx0 = __floats2half2_rn(xm.x, xm.y);
        __half2 hx1 = __floats2half2_rn(xm.z, xm.w);
        uint2 oxh;
        oxh.x = *(uint32_t*)&hx0;
        oxh.y = *(uint32_t*)&hx1;
        *(uint2*)(xh + (size_t)nl * CC + c0) = oxh;
    }

    // vectorized depthwise weights: 12 contiguous floats, 16B aligned
    const float4* wp4 = (const float4*)(dw_w + c0 * 3);
    float4 q0 = wp4[0], q1 = wp4[1], q2 = wp4[2];
    float4 db = *(const float4*)(dw_b + c0);
    float v[4];
    v[0] = db.x + xl.x * q0.x + xm.x * q0.y + xr.x * q0.z;
    v[1] = db.y + xl.y * q0.w + xm.y * q1.x + xr.y * q1.y;
    v[2] = db.z + xl.z * q1.z + xm.z * q1.w + xr.z * q2.x;
    v[3] = db.w + xl.w * q2.y + xm.w * q2.z + xr.w * q2.w;

    float s  = v[0] + v[1] + v[2] + v[3];
    float s2 = v[0]*v[0] + v[1]*v[1] + v[2]*v[2] + v[3]*v[3];
#pragma unroll
    for (int o = 16; o; o >>= 1) {
        s  += __shfl_xor_sync(0xFFFFFFFFu, s,  o);
        s2 += __shfl_xor_sync(0xFFFFFFFFu, s2, o);
    }
    __shared__ float rs[2][8], rs2[2][8];
    __shared__ float stats[2][2];
    if (lane == 0) { rs[half][wlocal] = s; rs2[half][wlocal] = s2; }
    __syncthreads();
    if (tid == 0) {
        float S = 0.f, S2 = 0.f;
#pragma unroll
        for (int w = 0; w < 8; ++w) { S += rs[half][w]; S2 += rs2[half][w]; }
        float mu = S * (1.f / CC);
        float var = S2 * (1.f / CC) - mu * mu;
        stats[half][0] = mu;
        stats[half][1] = rsqrtf(var + 1e-5f);
    }
    __syncthreads();
    const float mu = stats[half][0], rstd = stats[half][1];

    float4 lg = *(const float4*)(ln_g + c0);
    float4 lb = *(const float4*)(ln_b + c0);
    float g0, g1, g2, g3, h;
    h = (v[0] - mu) * rstd * lg.x + lb.x;
    g0 = 0.5f * h * (1.f + erff(h * 0.70710678118654752f));
    h = (v[1] - mu) * rstd * lg.y + lb.y;
    g1 = 0.5f * h * (1.f + erff(h * 0.70710678118654752f));
    h = (v[2] - mu) * rstd * lg.z + lb.z;
    g2 = 0.5f * h * (1.f + erff(h * 0.70710678118654752f));
    h = (v[3] - mu) * rstd * lg.w + lb.w;
    g3 = 0.5f * h * (1.f + erff(h * 0.70710678118654752f));

    __half2 h0 = __floats2half2_rn(g0, g1);
    __half2 h1 = __floats2half2_rn(g2, g3);
    uint2 ov;
    ov.x = *(uint32_t*)&h0;
    ov.y = *(uint32_t*)&h1;
    *(uint2*)(xdw + (size_t)nl * CC + c0) = ov;
}

// ---------------------------------------------------------------------------
// Kernel B: offset/mask heads (fp16 weights) + softmax + positions.
// FOUR positions per warp (weights loaded once, applied to 4 activations) —
// amortizes the dominant Wo/Wm read traffic 4x. 8 warps/block, no syncs.
// ---------------------------------------------------------------------------
__global__ __launch_bounds__(256)
void heads_pos(const __half* __restrict__ xdw,
               const __half* __restrict__ Woh, const float* __restrict__ bo,
               const __half* __restrict__ Wmh, const float* __restrict__ bmv,
               float* __restrict__ recw, int* __restrict__ reci) {
    const int wid  = threadIdx.x >> 5;
    const int lane = threadIdx.x & 31;
    const int pos0 = blockIdx.x * 32 + wid * 4;

    const __half2* xr0 = (const __half2*)(xdw + (size_t)pos0 * CC);
    const __half2* wo2 = (const __half2*)Woh;
    const __half2* wm2 = (const __half2*)Wmh;

    float p[4][14];
#pragma unroll
    for (int q = 0; q < 4; ++q)
#pragma unroll
        for (int j = 0; j < 14; ++j) p[q][j] = 0.f;

#pragma unroll 4
    for (int i = 0; i < 16; ++i) {
        int c2 = lane + 32 * i;
        float2 f[4];
#pragma unroll
        for (int q = 0; q < 4; ++q)
            f[q] = __half22float2(xr0[q * 512 + c2]);
#pragma unroll
        for (int j = 0; j < 7; ++j) {
            float2 w1 = __half22float2(wo2[j * 512 + c2]);
            float2 w2 = __half22float2(wm2[j * 512 + c2]);
#pragma unroll
            for (int q = 0; q < 4; ++q) {
                p[q][j]     = fmaf(f[q].x, w1.x, fmaf(f[q].y, w1.y, p[q][j]));
                p[q][7 + j] = fmaf(f[q].x, w2.x, fmaf(f[q].y, w2.y, p[q][7 + j]));
            }
        }
    }
#pragma unroll
    for (int o = 16; o; o >>= 1)
#pragma unroll
        for (int q = 0; q < 4; ++q)
#pragma unroll
            for (int j = 0; j < 14; ++j)
                p[q][j] += __shfl_xor_sync(0xFFFFFFFFu, p[q][j], o);

    if (lane == 0) {
#pragma unroll 1
        for (int q = 0; q < 4; ++q) {
            const int pos = pos0 + q;
            const int l   = pos & (LL - 1);
            float ho[KK], hm[KK];
#pragma unroll
            for (int j = 0; j < KK; ++j) {
                ho[j] = (p[q][j] + bo[j]) * 2.0f;     // OFFSET_SCALE
                hm[j] = p[q][7 + j] + bmv[j];
            }
            float mx = hm[0];
#pragma unroll
            for (int j = 1; j < KK; ++j) mx = fmaxf(mx, hm[j]);
            float e[KK], se = 0.f;
#pragma unroll
            for (int j = 0; j < KK; ++j) { e[j] = expf(hm[j] - mx); se += e[j]; }
            float inv = 1.f / se;

            float* rw = recw + (size_t)pos * 16;
            int*   ri = reci + (size_t)pos * 16;
#pragma unroll
            for (int k = 0; k < KK; ++k) {
                float mask = e[k] * inv;
                float ap  = (float)l + (float)(k - 3) + ho[k];
                float apc = fminf(fmaxf(ap, 0.f), (float)(LL - 1));
                int pf = (int)apc;
                if (pf > LL - 1) pf = LL - 1;
                int pc = pf + 1; if (pc > LL - 1) pc = LL - 1;
                float wc = apc - (float)pf;
                float wf = 1.f - wc;
                float valid = (ap < 0.f || ap > (float)(LL - 1)) ? 0.f : 1.f;
                rw[k]     = wf * valid * mask;
                rw[8 + k] = wc * valid * mask;
                ri[k]     = pf;
                ri[8 + k] = pc;
            }
            rw[7] = 0.f; rw[15] = 0.f;     // unused slots -> zero weight
            ri[7] = 0;   ri[15] = 0;
        }
    }
}

// ---------------------------------------------------------------------------
// Kernel C: gather-blend from fp16 x_proj -> sampled fp16.
// One block (128 thr) per position, 8 channels per thread; vectorized
// record loads (float4/int4 broadcasts).
// ---------------------------------------------------------------------------
__global__ __launch_bounds__(128)
void gather_blend(const __half* __restrict__ xph,
                  const float* __restrict__ recw, const int* __restrict__ reci,
                  __half* __restrict__ samp) {
    const int nl = blockIdx.x;
    const int n  = nl >> 11;
    const int c0 = threadIdx.x * 8;

    const float4* rw4 = (const float4*)(recw + (size_t)nl * 16);
    const int4*   ri4 = (const int4*)(reci + (size_t)nl * 16);

    float4 wfa = rw4[0], wfb = rw4[1];   // wf[0..7]
    float4 wca = rw4[2], wcb = rw4[3];   // wc[0..7]
    int4   pfa = ri4[0], pfb = ri4[1];   // pf[0..7]
    int4   pca = ri4[2], pcb = ri4[3];   // pc[0..7]

    float wf[8] = {wfa.x, wfa.y, wfa.z, wfa.w, wfb.x, wfb.y, wfb.z, wfb.w};
    float wc[8] = {wca.x, wca.y, wca.z, wca.w, wcb.x, wcb.y, wcb.z, wcb.w};
    int   pf[8] = {pfa.x, pfa.y, pfa.z, pfa.w, pfb.x, pfb.y, pfb.z, pfb.w};
    int   pc[8] = {pca.x, pca.y, pca.z, pca.w, pcb.x, pcb.y, pcb.z, pcb.w};

    const __half* xpn = xph + (size_t)n * LL * CC + c0;

    float acc[8];
#pragma unroll
    for (int m = 0; m < 8; ++m) acc[m] = 0.f;

#pragma unroll
    for (int k = 0; k < KK; ++k) {
        uint4 rf = *(const uint4*)(xpn + (size_t)pf[k] * CC);
        uint4 rc = *(const uint4*)(xpn + (size_t)pc[k] * CC);
        float w0 = wf[k], w1 = wc[k];
        const __half2* hf = (const __half2*)&rf;
        const __half2* hc = (const __half2*)&rc;
#pragma unroll
        for (int m = 0; m < 4; ++m) {
            float2 ff = __half22float2(hf[m]);
            float2 fc = __half22float2(hc[m]);
            acc[2*m + 0] = fmaf(ff.x, w0, fmaf(fc.x, w1, acc[2*m + 0]));
            acc[2*m + 1] = fmaf(ff.y, w0, fmaf(fc.y, w1, acc[2*m + 1]));
        }
    }

    uint4 ov;
    __half2 o0 = __floats2half2_rn(acc[0], acc[1]);
    __half2 o1 = __floats2half2_rn(acc[2], acc[3]);
    __half2 o2 = __floats2half2_rn(acc[4], acc[5]);
    __half2 o3 = __floats2half2_rn(acc[6], acc[7]);
    ov.x = *(uint32_t*)&o0; ov.y = *(uint32_t*)&o1;
    ov.z = *(uint32_t*)&o2; ov.w = *(uint32_t*)&o3;
    *(uint4*)(samp + (size_t)nl * CC + c0) = ov;
}

// ---------------------------------------------------------------------------
// Launch — R13 schedule (best known):
//
//   main: A(x->xh,xdw) -[evA]-> (wait evW) GEMM1 -[wait evB]-> C -> GEMM2
//   side: cvt_wi -[evW]-> cvt_wo, cvt_wo7, cvt_wm7 -(wait evA)-> B -[evB]
// ---------------------------------------------------------------------------
extern "C" void kernel_launch(void* const* d_in, const int* in_sizes, int n_in,
                              void* d_out, int out_size) {
    const float* x    = (const float*)d_in[0];
    const float* Wi   = (const float*)d_in[1];
    const float* bi   = (const float*)d_in[2];
    const float* dw_w = (const float*)d_in[3];
    const float* dw_b = (const float*)d_in[4];
    const float* ln_g = (const float*)d_in[5];
    const float* ln_b = (const float*)d_in[6];
    const float* Wo   = (const float*)d_in[7];
    const float* bo   = (const float*)d_in[8];
    const float* Wm   = (const float*)d_in[9];
    const float* bmv  = (const float*)d_in[10];
    const float* Wout = (const float*)d_in[11];
    const float* bout = (const float*)d_in[12];
    float* out = (float*)d_out;

    __half *xh, *wih, *woh, *woh7, *wmh7, *xph, *xdw, *samph;
    float *recw;
    int *reci;
    cudaGetSymbolAddress((void**)&xh,    g_xh);
    cudaGetSymbolAddress((void**)&wih,   g_wih);
    cudaGetSymbolAddress((void**)&woh,   g_woh);
    cudaGetSymbolAddress((void**)&woh7,  g_woh7);
    cudaGetSymbolAddress((void**)&wmh7,  g_wmh7);
    cudaGetSymbolAddress((void**)&xph,   g_xph);
    cudaGetSymbolAddress((void**)&xdw,   g_xdw);
    cudaGetSymbolAddress((void**)&samph, g_samph);
    cudaGetSymbolAddress((void**)&recw,  g_recw);
    cudaGetSymbolAddress((void**)&reci,  g_reci);

    cudaFuncSetAttribute(mma_gemm<__half>,
                         cudaFuncAttributeMaxDynamicSharedMemorySize, SMEM_F16);
    cudaFuncSetAttribute(mma_gemm<float>,
                         cudaFuncAttributeMaxDynamicSharedMemorySize, SMEM_F16);

    // One-time host-side stream/event creation (no device memory involved).
    static cudaStream_t s_side = nullptr;
    static cudaEvent_t  ev_fork = nullptr, ev_w = nullptr, ev_a = nullptr,
                        ev_b = nullptr;
    if (s_side == nullptr) {
        int lo = 0, hi = 0;
        cudaDeviceGetStreamPriorityRange(&lo, &hi);
        cudaStreamCreateWithPriority(&s_side, cudaStreamNonBlocking, lo);
        cudaEventCreateWithFlags(&ev_fork, cudaEventDisableTiming);
        cudaEventCreateWithFlags(&ev_w,    cudaEventDisableTiming);
        cudaEventCreateWithFlags(&ev_a,    cudaEventDisableTiming);
        cudaEventCreateWithFlags(&ev_b,    cudaEventDisableTiming);
    }

    dim3 gemm_grid(CC / 128, MM / 128);   // (8, 64)

    // Fork side stream off the main (legacy) stream.
    cudaEventRecord(ev_fork, 0);
    cudaStreamWaitEvent(s_side, ev_fork, 0);

    // side: cvt Wi first (GEMM1 gate), then other weight cvts
    cvt_f16<<<(CC * CC / 4) / 256, 256, 0, s_side>>>(
        (const float4*)Wi, (uint2*)wih, CC * CC / 4);
    cudaEventRecord(ev_w, s_side);
    cvt_f16<<<(CC * CC / 4) / 256, 256, 0, s_side>>>(
        (const float4*)Wout, (uint2*)woh, CC * CC / 4);
    cvt_f16<<<(KK * CC / 4 + 255) / 256, 256, 0, s_side>>>(
        (const float4*)Wo, (uint2*)woh7, KK * CC / 4);
    cvt_f16<<<(KK * CC / 4 + 255) / 256, 256, 0, s_side>>>(
        (const float4*)Wm, (uint2*)wmh7, KK * CC / 4);

    // main: A immediately (no weight dependency), emits xh + xdw
    conv_ln_gelu<<<MM / 2, 512>>>(x, dw_w, dw_b, ln_g, ln_b, xdw, xh);
    cudaEventRecord(ev_a, 0);

    // side: B after A (needs xdw; head weights converted above in-stream)
    cudaStreamWaitEvent(s_side, ev_a, 0);
    heads_pos<<<MM / 32, 256, 0, s_side>>>(xdw, woh7, bo, wmh7, bmv,
                                           recw, reci);
    cudaEventRecord(ev_b, s_side);

    // main: GEMM1 (after cvt_wi; overlaps B), then join, C, GEMM2
    cudaStreamWaitEvent(0, ev_w, 0);
    mma_gemm<__half><<<gemm_grid, 256, SMEM_F16>>>(xh, wih, bi, xph);
    cudaStreamWaitEvent(0, ev_b, 0);   // also orders woh (side, pre-B)
    gather_blend<<<MM, 128>>>(xph, recw, reci, samph);
    mma_gemm<float><<<gemm_grid, 256, SMEM_F16>>>(samph, woh, bout, out);
}

// round 15
// speedup vs baseline: 1.2346x; 1.2346x over previous
#include <cuda_runtime.h>
#include <cuda_fp16.h>
#include <math.h>
#include <stdint.h>

// Problem constants
#define NB   4
#define LL   2048
#define CC   1024
#define KK   7
#define MM   (NB * LL)   // 8192

// Scratch (allocation-free rule: __device__ globals)
__device__ __half g_xh[MM * CC];     // fp16 x (emitted by conv_ln_gelu)
__device__ __half g_wih[CC * CC];    // fp16 Wi
__device__ __half g_woh[CC * CC];    // fp16 Wout
__device__ __half g_woh7[KK * CC];   // fp16 Wo (offset head)
__device__ __half g_wmh7[KK * CC];   // fp16 Wm (mask head)
__device__ __half g_xph[MM * CC];    // x_proj (fp16)
__device__ __half g_xdw[MM * CC];    // conv+LN+GELU result (fp16)
__device__ __half g_samph[MM * CC];  // sampled (fp16)
__device__ float  g_recw[MM * 16];   // per-position blend weights (wf[8], wc[8])
__device__ int    g_reci[MM * 16];   // per-position gather indices (pf[8], pc[8])

// ---------------------------------------------------------------------------
// helpers
// ---------------------------------------------------------------------------
__device__ __forceinline__ uint32_t smem_u32(const void* p) {
    uint32_t a;
    asm("{ .reg .u64 t; cvta.to.shared.u64 t, %1; cvt.u32.u64 %0, t; }"
        : "=r"(a) : "l"(p));
    return a;
}

__device__ __forceinline__ void mma_f16(float* d, const uint32_t* a,
                                        const uint32_t* b) {
    asm volatile(
        "mma.sync.aligned.m16n8k16.row.col.f32.f16.f16.f32 "
        "{%0,%1,%2,%3}, {%4,%5,%6,%7}, {%8,%9}, {%0,%1,%2,%3};"
        : "+f"(d[0]), "+f"(d[1]), "+f"(d[2]), "+f"(d[3])
        : "r"(a[0]), "r"(a[1]), "r"(a[2]), "r"(a[3]),
          "r"(b[0]), "r"(b[1]));
}

#define LDSM4(r0, r1, r2, r3, addr)                                           \
    asm volatile("ldmatrix.sync.aligned.m8n8.x4.shared.b16 {%0,%1,%2,%3}, [%4];" \
                 : "=r"(r0), "=r"(r1), "=r"(r2), "=r"(r3) : "r"(addr))

#define CP_ASYNC16(dst, src) \
    asm volatile("cp.async.cg.shared.global [%0], [%1], 16;" :: "r"(dst), "l"(src))
#define CP_COMMIT() asm volatile("cp.async.commit_group;" ::: "memory")
#define CP_WAIT1()  asm volatile("cp.async.wait_group 1;" ::: "memory")

__device__ __forceinline__ void store_out(float2 v, float* p) {
    *(float2*)p = v;
}
__device__ __forceinline__ void store_out(float2 v, __half* p) {
    *(__half2*)p = __floats2half2_rn(v.x, v.y);
}

// ---------------------------------------------------------------------------
// fp32 -> fp16 conversion (weights)
// ---------------------------------------------------------------------------
__global__ __launch_bounds__(256)
void cvt_f16(const float4* __restrict__ in, uint2* __restrict__ out, int n4) {
    int i = blockIdx.x * blockDim.x + threadIdx.x;
    if (i < n4) {
        float4 v = in[i];
        __half2 h0 = __floats2half2_rn(v.x, v.y);
        __half2 h1 = __floats2half2_rn(v.z, v.w);
        uint2 o;
        o.x = *(uint32_t*)&h0;
        o.y = *(uint32_t*)&h1;
        out[i] = o;
    }
}

// ---------------------------------------------------------------------------
// fp16 mma.sync GEMM (NT): C[m,n] = sum_k A[m,k]*B[n,k] + bias[n]
// 128x128 CTA tile, BK=64, 8 warps (4x2), 32x64 warp tile, 256 threads,
// 3-stage cp.async, XOR swizzle, ldmatrix. Output templated.
// (Proven best configuration: ~54us/GEMM = fp32-accum HMMA ceiling.)
// ---------------------------------------------------------------------------
#define TILE_BYTES 16384
#define SMEM_F16   (3 * 2 * TILE_BYTES)

__device__ __forceinline__ void stage_ab(uint32_t base,
                                         const __half* __restrict__ A,
                                         const __half* __restrict__ B,
                                         int bm, int bn, int k0, int tid) {
#pragma unroll
    for (int i = 0; i < 4; ++i) {
        int f = i * 256 + tid;
        int row = f >> 3, c4 = f & 7;
        uint32_t dst = base + row * 128 + ((c4 ^ (row & 7)) << 4);
        const __half* src = A + (size_t)(bm + row) * 1024 + k0 + c4 * 8;
        CP_ASYNC16(dst, src);
    }
#pragma unroll
    for (int i = 0; i < 4; ++i) {
        int f = i * 256 + tid;
        int row = f >> 3, c4 = f & 7;
        uint32_t dst = base + TILE_BYTES + row * 128 + ((c4 ^ (row & 7)) << 4);
        const __half* src = B + (size_t)(bn + row) * 1024 + k0 + c4 * 8;
        CP_ASYNC16(dst, src);
    }
}

template <typename OT>
__global__ __launch_bounds__(256, 2)
void mma_gemm(const __half* __restrict__ A, const __half* __restrict__ B,
              const float* __restrict__ bias, OT* __restrict__ Cout) {
    extern __shared__ char dyn_smem[];
    const uint32_t sb = smem_u32(dyn_smem);

    const int tid  = threadIdx.x;
    const int wid  = tid >> 5;
    const int lane = tid & 31;
    const int g    = lane >> 2;
    const int tig  = lane & 3;
    const int wm   = wid >> 1;     // 0..3  (32 rows each)
    const int wn   = wid & 1;      // 0..1  (64 cols each)
    const int bm = blockIdx.y * 128;
    const int bn = blockIdx.x * 128;

    float d[2][8][4];
#pragma unroll
    for (int i = 0; i < 2; ++i)
#pragma unroll
        for (int j = 0; j < 8; ++j)
#pragma unroll
            for (int r = 0; r < 4; ++r) d[i][j][r] = 0.f;

    const int aHi = (lane >> 4) & 1;
    uint32_t aRowOff[2], aSw[2];
#pragma unroll
    for (int i = 0; i < 2; ++i) {
        int rowA = wm * 32 + i * 16 + (lane & 15);
        aRowOff[i] = (uint32_t)(rowA * 128);
        aSw[i] = (uint32_t)(rowA & 7);
    }
    const int bHi = (lane >> 3) & 1;
    uint32_t bRowOff[4], bSw[4];
#pragma unroll
    for (int j2 = 0; j2 < 4; ++j2) {
        int rowB = wn * 64 + j2 * 16 + ((lane & 16) >> 1) + (lane & 7);
        bRowOff[j2] = (uint32_t)(rowB * 128);
        bSw[j2] = (uint32_t)(rowB & 7);
    }

    stage_ab(sb + 0 * 32768, A, B, bm, bn, 0, tid);
    CP_COMMIT();
    stage_ab(sb + 1 * 32768, A, B, bm, bn, 64, tid);
    CP_COMMIT();

#pragma unroll 1
    for (int s = 0; s < 16; ++s) {
        CP_WAIT1();
        __syncthreads();

        if (s + 2 < 16)
            stage_ab(sb + ((s + 2) % 3) * 32768, A, B, bm, bn,
                     (s + 2) * 64, tid);
        CP_COMMIT();

        const uint32_t aBase = sb + (s % 3) * 32768;
        const uint32_t bBase = aBase + TILE_BYTES;

#pragma unroll
        for (int ks = 0; ks < 4; ++ks) {
            const uint32_t granA = (uint32_t)(2 * ks + aHi);
            const uint32_t granB = (uint32_t)(2 * ks + bHi);
            uint32_t af[2][4];
#pragma unroll
            for (int i = 0; i < 2; ++i) {
                uint32_t addr = aBase + aRowOff[i] + ((granA ^ aSw[i]) << 4);
                LDSM4(af[i][0], af[i][1], af[i][2], af[i][3], addr);
            }
            uint32_t bf[8][2];
#pragma unroll
            for (int j2 = 0; j2 < 4; ++j2) {
                uint32_t addr = bBase + bRowOff[j2] + ((granB ^ bSw[j2]) << 4);
                LDSM4(bf[2 * j2][0], bf[2 * j2][1],
                      bf[2 * j2 + 1][0], bf[2 * j2 + 1][1], addr);
            }
#pragma unroll
            for (int i = 0; i < 2; ++i)
#pragma unroll
                for (int j = 0; j < 8; ++j)
                    mma_f16(d[i][j], af[i], bf[j]);
        }
    }

#pragma unroll
    for (int i = 0; i < 2; ++i) {
        int row = bm + wm * 32 + i * 16 + g;
        OT* o0 = Cout + (size_t)row * 1024 + bn + wn * 64;
        OT* o1 = o0 + 8 * 1024;
#pragma unroll
        for (int j = 0; j < 8; ++j) {
            int col = j * 8 + tig * 2;
            float2 bb = *(const float2*)&bias[bn + wn * 64 + col];
            float2 v0, v1;
            v0.x = d[i][j][0] + bb.x;
            v0.y = d[i][j][1] + bb.y;
            v1.x = d[i][j][2] + bb.x;
            v1.y = d[i][j][3] + bb.y;
            store_out(v0, o0 + col);
            store_out(v1, o1 + col);
        }
    }
}

// ---------------------------------------------------------------------------
// Kernel A (R13 champion version): depthwise conv(k=3,pad=1) + LayerNorm +
// exact GELU -> x_dw fp16, plus fp16 copy of its own x row (feeds GEMM1).
// One block (256 thr) per (n,l); 4 channels per thread.
// ---------------------------------------------------------------------------
__global__ __launch_bounds__(256)
void conv_ln_gelu(const float* __restrict__ x,
                  const float* __restrict__ dw_w, const float* __restrict__ dw_b,
                  const float* __restrict__ ln_g, const float* __restrict__ ln_b,
                  __half* __restrict__ xdw, __half* __restrict__ xh) {
    const int nl = blockIdx.x;
    const int l = nl & (LL - 1);
    const int tid = threadIdx.x;
    const int lane = tid & 31;
    const int wid = tid >> 5;
    const int c0 = tid * 4;

    const float* x0 = x + (size_t)nl * CC;

    float4 xm = *(const float4*)(x0 + c0);
    float4 xl = (l > 0)      ? *(const float4*)(x0 + c0 - CC) : make_float4(0,0,0,0);
    float4 xr = (l < LL - 1) ? *(const float4*)(x0 + c0 + CC) : make_float4(0,0,0,0);

    // emit fp16 copy of this row (feeds GEMM1)
    {
        __half2 hx0 = __floats2half2_rn(xm.x, xm.y);
        __half2 hx1 = __floats2half2_rn(xm.z, xm.w);
        uint2 oxh;
        oxh.x = *(uint32_t*)&hx0;
        oxh.y = *(uint32_t*)&hx1;
        *(uint2*)(xh + (size_t)nl * CC + c0) = oxh;
    }

    // vectorized depthwise weights: 12 contiguous floats, 16B aligned
    const float4* wp4 = (const float4*)(dw_w + c0 * 3);
    float4 q0 = wp4[0], q1 = wp4[1], q2 = wp4[2];
    float4 db = *(const float4*)(dw_b + c0);
    float v[4];
    v[0] = db.x + xl.x * q0.x + xm.x * q0.y + xr.x * q0.z;
    v[1] = db.y + xl.y * q0.w + xm.y * q1.x + xr.y * q1.y;
    v[2] = db.z + xl.z * q1.z + xm.z * q1.w + xr.z * q2.x;
    v[3] = db.w + xl.w * q2.y + xm.w * q2.z + xr.w * q2.w;

    float s  = v[0] + v[1] + v[2] + v[3];
    float s2 = v[0]*v[0] + v[1]*v[1] + v[2]*v[2] + v[3]*v[3];
#pragma unroll
    for (int o = 16; o; o >>= 1) {
        s  += __shfl_xor_sync(0xFFFFFFFFu, s,  o);
        s2 += __shfl_xor_sync(0xFFFFFFFFu, s2, o);
    }
    __shared__ float rs[8], rs2[8];
    __shared__ float stats[2];
    if (lane == 0) { rs[wid] = s; rs2[wid] = s2; }
    __syncthreads();
    if (tid == 0) {
        float S = 0.f, S2 = 0.f;
#pragma unroll
        for (int w = 0; w < 8; ++w) { S += rs[w]; S2 += rs2[w]; }
        float mu = S * (1.f / CC);
        float var = S2 * (1.f / CC) - mu * mu;
        stats[0] = mu;
        stats[1] = rsqrtf(var + 1e-5f);
    }
    __syncthreads();
    const float mu = stats[0], rstd = stats[1];

    float4 lg = *(const float4*)(ln_g + c0);
    float4 lb = *(const float4*)(ln_b + c0);
    float g0, g1, g2, g3, h;
    h = (v[0] - mu) * rstd * lg.x + lb.x;
    g0 = 0.5f * h * (1.f + erff(h * 0.70710678118654752f));
    h = (v[1] - mu) * rstd * lg.y + lb.y;
    g1 = 0.5f * h * (1.f + erff(h * 0.70710678118654752f));
    h = (v[2] - mu) * rstd * lg.z + lb.z;
    g2 = 0.5f * h * (1.f + erff(h * 0.70710678118654752f));
    h = (v[3] - mu) * rstd * lg.w + lb.w;
    g3 = 0.5f * h * (1.f + erff(h * 0.70710678118654752f));

    __half2 h0 = __floats2half2_rn(g0, g1);
    __half2 h1 = __floats2half2_rn(g2, g3);
    uint2 ov;
    ov.x = *(uint32_t*)&h0;
    ov.y = *(uint32_t*)&h1;
    *(uint2*)(xdw + (size_t)nl * CC + c0) = ov;
}

// ---------------------------------------------------------------------------
// Kernel B (R13 champion version): offset/mask heads (fp16 weights) +
// softmax + positions. Warp per position, 8 per block, no __syncthreads.
// ---------------------------------------------------------------------------
__global__ __launch_bounds__(256)
void heads_pos(const __half* __restrict__ xdw,
               const __half* __restrict__ Woh, const float* __restrict__ bo,
               const __half* __restrict__ Wmh, const float* __restrict__ bmv,
               float* __restrict__ recw, int* __restrict__ reci) {
    const int wid  = threadIdx.x >> 5;
    const int lane = threadIdx.x & 31;
    const int pos  = blockIdx.x * 8 + wid;
    const int l    = pos & (LL - 1);

    const __half2* xr  = (const __half2*)(xdw + (size_t)pos * CC);
    const __half2* wo2 = (const __half2*)Woh;
    const __half2* wm2 = (const __half2*)Wmh;

    float p[14];
#pragma unroll
    for (int j = 0; j < 14; ++j) p[j] = 0.f;

#pragma unroll
    for (int i = 0; i < 16; ++i) {
        int c2 = lane + 32 * i;
        float2 f = __half22float2(xr[c2]);
#pragma unroll
        for (int j = 0; j < 7; ++j) {
            float2 w1 = __half22float2(wo2[j * 512 + c2]);
            float2 w2 = __half22float2(wm2[j * 512 + c2]);
            p[j]     = fmaf(f.x, w1.x, fmaf(f.y, w1.y, p[j]));
            p[7 + j] = fmaf(f.x, w2.x, fmaf(f.y, w2.y, p[7 + j]));
        }
    }
#pragma unroll
    for (int o = 16; o; o >>= 1)
#pragma unroll
        for (int j = 0; j < 14; ++j)
            p[j] += __shfl_xor_sync(0xFFFFFFFFu, p[j], o);

    if (lane == 0) {
        float ho[KK], hm[KK];
#pragma unroll
        for (int j = 0; j < KK; ++j) {
            ho[j] = (p[j] + bo[j]) * 2.0f;     // OFFSET_SCALE
            hm[j] = p[7 + j] + bmv[j];
        }
        float mx = hm[0];
#pragma unroll
        for (int j = 1; j < KK; ++j) mx = fmaxf(mx, hm[j]);
        float e[KK], se = 0.f;
#pragma unroll
        for (int j = 0; j < KK; ++j) { e[j] = expf(hm[j] - mx); se += e[j]; }
        float inv = 1.f / se;

        float* rw = recw + (size_t)pos * 16;
        int*   ri = reci + (size_t)pos * 16;
#pragma unroll
        for (int k = 0; k < KK; ++k) {
            float mask = e[k] * inv;
            float ap  = (float)l + (float)(k - 3) + ho[k];
            float apc = fminf(fmaxf(ap, 0.f), (float)(LL - 1));
            int pf = (int)apc;
            if (pf > LL - 1) pf = LL - 1;
            int pc = pf + 1; if (pc > LL - 1) pc = LL - 1;
            float wc = apc - (float)pf;
            float wf = 1.f - wc;
            float valid = (ap < 0.f || ap > (float)(LL - 1)) ? 0.f : 1.f;
            rw[k]     = wf * valid * mask;
            rw[8 + k] = wc * valid * mask;
            ri[k]     = pf;
            ri[8 + k] = pc;
        }
        rw[7] = 0.f; rw[15] = 0.f;     // unused slots -> zero weight
        ri[7] = 0;   ri[15] = 0;
    }
}

// ---------------------------------------------------------------------------
// Kernel C: gather-blend from fp16 x_proj -> sampled fp16.
// 256-thread block handles TWO positions (independent 128-thread halves,
// no syncs, per-thread code identical to champion). Halves block count.
// ---------------------------------------------------------------------------
__global__ __launch_bounds__(256)
void gather_blend(const __half* __restrict__ xph,
                  const float* __restrict__ recw, const int* __restrict__ reci,
                  __half* __restrict__ samp) {
    const int half = threadIdx.x >> 7;            // 0 or 1
    const int nl = blockIdx.x * 2 + half;
    const int n  = nl >> 11;
    const int c0 = (threadIdx.x & 127) * 8;

    const float4* rw4 = (const float4*)(recw + (size_t)nl * 16);
    const int4*   ri4 = (const int4*)(reci + (size_t)nl * 16);

    float4 wfa = rw4[0], wfb = rw4[1];   // wf[0..7]
    float4 wca = rw4[2], wcb = rw4[3];   // wc[0..7]
    int4   pfa = ri4[0], pfb = ri4[1];   // pf[0..7]
    int4   pca = ri4[2], pcb = ri4[3];   // pc[0..7]

    float wf[8] = {wfa.x, wfa.y, wfa.z, wfa.w, wfb.x, wfb.y, wfb.z, wfb.w};
    float wc[8] = {wca.x, wca.y, wca.z, wca.w, wcb.x, wcb.y, wcb.z, wcb.w};
    int   pf[8] = {pfa.x, pfa.y, pfa.z, pfa.w, pfb.x, pfb.y, pfb.z, pfb.w};
    int   pc[8] = {pca.x, pca.y, pca.z, pca.w, pcb.x, pcb.y, pcb.z, pcb.w};

    const __half* xpn = xph + (size_t)n * LL * CC + c0;

    float acc[8];
#pragma unroll
    for (int m = 0; m < 8; ++m) acc[m] = 0.f;

#pragma unroll
    for (int k = 0; k < KK; ++k) {
        uint4 rf = *(const uint4*)(xpn + (size_t)pf[k] * CC);
        uint4 rc = *(const uint4*)(xpn + (size_t)pc[k] * CC);
        float w0 = wf[k], w1 = wc[k];
        const __half2* hf = (const __half2*)&rf;
        const __half2* hc = (const __half2*)&rc;
#pragma unroll
        for (int m = 0; m < 4; ++m) {
            float2 ff = __half22float2(hf[m]);
            float2 fc = __half22float2(hc[m]);
            acc[2*m + 0] = fmaf(ff.x, w0, fmaf(fc.x, w1, acc[2*m + 0]));
            acc[2*m + 1] = fmaf(ff.y, w0, fmaf(fc.y, w1, acc[2*m + 1]));
        }
    }

    uint4 ov;
    __half2 o0 = __floats2half2_rn(acc[0], acc[1]);
    __half2 o1 = __floats2half2_rn(acc[2], acc[3]);
    __half2 o2 = __floats2half2_rn(acc[4], acc[5]);
    __half2 o3 = __floats2half2_rn(acc[6], acc[7]);
    ov.x = *(uint32_t*)&o0; ov.y = *(uint32_t*)&o1;
    ov.z = *(uint32_t*)&o2; ov.w = *(uint32_t*)&o3;
    *(uint4*)(samp + (size_t)nl * CC + c0) = ov;
}

// ---------------------------------------------------------------------------
// Launch — R13 schedule (champion):
//
//   main: A(x->xh,xdw) -[evA]-> (wait evW) GEMM1 -[wait evB]-> C -> GEMM2
//   side: cvt_wi -[evW]-> cvt_wo, cvt_wo7, cvt_wm7 -(wait evA)-> B -[evB]
// ---------------------------------------------------------------------------
extern "C" void kernel_launch(void* const* d_in, const int* in_sizes, int n_in,
                              void* d_out, int out_size) {
    const float* x    = (const float*)d_in[0];
    const float* Wi   = (const float*)d_in[1];
    const float* bi   = (const float*)d_in[2];
    const float* dw_w = (const float*)d_in[3];
    const float* dw_b = (const float*)d_in[4];
    const float* ln_g = (const float*)d_in[5];
    const float* ln_b = (const float*)d_in[6];
    const float* Wo   = (const float*)d_in[7];
    const float* bo   = (const float*)d_in[8];
    const float* Wm   = (const float*)d_in[9];
    const float* bmv  = (const float*)d_in[10];
    const float* Wout = (const float*)d_in[11];
    const float* bout = (const float*)d_in[12];
    float* out = (float*)d_out;

    __half *xh, *wih, *woh, *woh7, *wmh7, *xph, *xdw, *samph;
    float *recw;
    int *reci;
    cudaGetSymbolAddress((void**)&xh,    g_xh);
    cudaGetSymbolAddress((void**)&wih,   g_wih);
    cudaGetSymbolAddress((void**)&woh,   g_woh);
    cudaGetSymbolAddress((void**)&woh7,  g_woh7);
    cudaGetSymbolAddress((void**)&wmh7,  g_wmh7);
    cudaGetSymbolAddress((void**)&xph,   g_xph);
    cudaGetSymbolAddress((void**)&xdw,   g_xdw);
    cudaGetSymbolAddress((void**)&samph, g_samph);
    cudaGetSymbolAddress((void**)&recw,  g_recw);
    cudaGetSymbolAddress((void**)&reci,  g_reci);

    cudaFuncSetAttribute(mma_gemm<__half>,
                         cudaFuncAttributeMaxDynamicSharedMemorySize, SMEM_F16);
    cudaFuncSetAttribute(mma_gemm<float>,
                         cudaFuncAttributeMaxDynamicSharedMemorySize, SMEM_F16);

    // One-time host-side stream/event creation (no device memory involved).
    static cudaStream_t s_side = nullptr;
    static cudaEvent_t  ev_fork = nullptr, ev_w = nullptr, ev_a = nullptr,
                        ev_b = nullptr;
    if (s_side == nullptr) {
        int lo = 0, hi = 0;
        cudaDeviceGetStreamPriorityRange(&lo, &hi);
        cudaStreamCreateWithPriority(&s_side, cudaStreamNonBlocking, lo);
        cudaEventCreateWithFlags(&ev_fork, cudaEventDisableTiming);
        cudaEventCreateWithFlags(&ev_w,    cudaEventDisableTiming);
        cudaEventCreateWithFlags(&ev_a,    cudaEventDisableTiming);
        cudaEventCreateWithFlags(&ev_b,    cudaEventDisableTiming);
    }

    dim3 gemm_grid(CC / 128, MM / 128);   // (8, 64)

    // Fork side stream off the main (legacy) stream.
    cudaEventRecord(ev_fork, 0);
    cudaStreamWaitEvent(s_side, ev_fork, 0);

    // side: cvt Wi first (GEMM1 gate), then other weight cvts
    cvt_f16<<<(CC * CC / 4) / 256, 256, 0, s_side>>>(
        (const float4*)Wi, (uint2*)wih, CC * CC / 4);
    cudaEventRecord(ev_w, s_side);
    cvt_f16<<<(CC * CC / 4) / 256, 256, 0, s_side>>>(
        (const float4*)Wout, (uint2*)woh, CC * CC / 4);
    cvt_f16<<<(KK * CC / 4 + 255) / 256, 256, 0, s_side>>>(
        (const float4*)Wo, (uint2*)woh7, KK * CC / 4);
    cvt_f16<<<(KK * CC / 4 + 255) / 256, 256, 0, s_side>>>(
        (const float4*)Wm, (uint2*)wmh7, KK * CC / 4);

    // main: A immediately (no weight dependency), emits xh + xdw
    conv_ln_gelu<<<MM, 256>>>(x, dw_w, dw_b, ln_g, ln_b, xdw, xh);
    cudaEventRecord(ev_a, 0);

    // side: B after A (needs xdw; head weights converted above in-stream)
    cudaStreamWaitEvent(s_side, ev_a, 0);
    heads_pos<<<MM / 8, 256, 0, s_side>>>(xdw, woh7, bo, wmh7, bmv, recw, reci);
    cudaEventRecord(ev_b, s_side);

    // main: GEMM1 (after cvt_wi; overlaps B), then join, C, GEMM2
    cudaStreamWaitEvent(0, ev_w, 0);
    mma_gemm<__half><<<gemm_grid, 256, SMEM_F16>>>(xh, wih, bi, xph);
    cudaStreamWaitEvent(0, ev_b, 0);   // also orders woh (side, pre-B)
    gather_blend<<<MM / 2, 256>>>(xph, recw, reci, samph);
    mma_gemm<float><<<gemm_grid, 256, SMEM_F16>>>(samph, woh, bout, out);
}